// round 1
// baseline (speedup 1.0000x reference)
#include <cuda_runtime.h>

// Quanvolution (K=2, 4 qubits, Ry encoding + Ry params + CNOT ring, <Z_q>).
// Analytic collapse:
//   phi_i = pi*pix_i + w_i
//   CNOT ring is a basis permutation; <Z_q> factorizes into products of cos(phi_i)
//   over the XOR-support S_q of output bit q:
//     S_0={1,2,3}, S_1={0,1}, S_2={0,1,2}, S_3={0,1,2,3}
// Pixel->qubit mapping within the 2x2 patch (dx,dy): (0,0)->0 (0,1)->1 (1,0)->2 (1,1)->3.

#define IN_H 224
#define IN_W 224
#define LX   223
#define LY   223

__global__ __launch_bounds__(224) void quanv_kernel(
    const float* __restrict__ in,   // (B,1,224,224)
    const float* __restrict__ wt,   // (1,4)
    float* __restrict__ out)        // (B,4,223,223)
{
    const int x = blockIdx.x;       // output row [0,223)
    const int b = blockIdx.y;       // batch
    const int y = threadIdx.x;      // [0,224)

    __shared__ float r0[IN_W];
    __shared__ float r1[IN_W];

    const float* base = in + (size_t)b * (IN_H * IN_W) + (size_t)x * IN_W;
    r0[y] = base[y];
    r1[y] = base[IN_W + y];

    const float w0 = __ldg(&wt[0]);
    const float w1 = __ldg(&wt[1]);
    const float w2 = __ldg(&wt[2]);
    const float w3 = __ldg(&wt[3]);

    __syncthreads();

    if (y < LY) {
        const float PI = 3.14159265358979323846f;
        float g0 = __cosf(fmaf(PI, r0[y],     w0));
        float g1 = __cosf(fmaf(PI, r0[y + 1], w1));
        float g2 = __cosf(fmaf(PI, r1[y],     w2));
        float g3 = __cosf(fmaf(PI, r1[y + 1], w3));

        float g01  = g0 * g1;
        float g12  = g1 * g2;
        float g012 = g01 * g2;

        const size_t plane = (size_t)LX * LY;
        size_t o = (size_t)b * 4 * plane + (size_t)x * LY + y;
        out[o]             = g12 * g3;   // q0: g1 g2 g3
        out[o + plane]     = g01;        // q1: g0 g1
        out[o + 2 * plane] = g012;       // q2: g0 g1 g2
        out[o + 3 * plane] = g012 * g3;  // q3: g0 g1 g2 g3
    }
}

extern "C" void kernel_launch(void* const* d_in, const int* in_sizes, int n_in,
                              void* d_out, int out_size)
{
    const float* in = (const float*)d_in[0];   // (64,1,224,224) float32
    const float* wt = (const float*)d_in[1];   // (1,4) float32
    float* out = (float*)d_out;                // (64,4,223,223) float32

    dim3 grid(LX, 64);
    quanv_kernel<<<grid, 224>>>(in, wt, out);
}

// round 10
// speedup vs baseline: 1.1189x; 1.1189x over previous
#include <cuda_runtime.h>

// Quanvolution (K=2, 4 qubits): analytic collapse to products of cos(pi*pix + w_q).
//   S_0={1,2,3}, S_1={0,1}, S_2={0,1,2}, S_3={0,1,2,3}
// R1 finding: 64MB working set is L2-resident (126MB L2) -> L2/latency bound,
// not HBM bound. TR=16 rows/block (2x ILP vs TR=8 at equal occupancy).
// Last row-tile is clamped to x0=207 and overlaps tile 12 by 15 rows:
// duplicate writes carry identical values (deterministic), letting every
// block run the branch-free fully-unrolled body.
// Output stores stay scalar (odd plane/row strides forbid wide STG).

#define IN_W 224
#define IN_H 224
#define LY   223
#define TR   16         // output rows per block

__global__ __launch_bounds__(224) void quanv_kernel(
    const float4* __restrict__ in4,  // (B,1,224,224) viewed as float4
    const float* __restrict__ wt,    // (1,4)
    float* __restrict__ out)         // (B,4,223,223)
{
    const int t  = blockIdx.x;             // row tile [0,14)
    const int b  = blockIdx.y;             // batch
    const int y  = threadIdx.x;            // [0,224)
    const int x0 = min(t * TR, LY - TR);   // clamp: last tile overlaps, stays full

    __shared__ float rows[TR + 1][IN_W];   // 17 x 224 floats = 15232 B

    // Stage TR+1 = 17 input rows (x0+16 <= 223 < IN_H, always in-bounds).
    const float4* base4 = in4 + ((size_t)b * IN_H + x0) * (IN_W / 4);
    float4* s4 = reinterpret_cast<float4*>(&rows[0][0]);
    #pragma unroll
    for (int f = 0; f < (TR + 1) * (IN_W / 4); f += 224) {
        int idx = f + y;
        if (idx < (TR + 1) * (IN_W / 4))
            s4[idx] = base4[idx];
    }

    const float w0 = wt[0];
    const float w1 = wt[1];
    const float w2 = wt[2];
    const float w3 = wt[3];

    __syncthreads();

    if (y < LY) {
        const float PI = 3.14159265358979323846f;
        const size_t plane = (size_t)LY * LY;
        float* o = out + (size_t)b * 4 * plane + (size_t)x0 * LY + y;

        #pragma unroll
        for (int r = 0; r < TR; r++) {
            float g0 = __cosf(fmaf(PI, rows[r][y],         w0));
            float g1 = __cosf(fmaf(PI, rows[r][y + 1],     w1));
            float g2 = __cosf(fmaf(PI, rows[r + 1][y],     w2));
            float g3 = __cosf(fmaf(PI, rows[r + 1][y + 1], w3));

            float g01  = g0 * g1;
            float g12  = g1 * g2;
            float g012 = g01 * g2;

            o[0]         = g12 * g3;   // q0
            o[plane]     = g01;        // q1
            o[2 * plane] = g012;       // q2
            o[3 * plane] = g012 * g3;  // q3

            o += LY;
        }
    }
}

extern "C" void kernel_launch(void* const* d_in, const int* in_sizes, int n_in,
                              void* d_out, int out_size)
{
    const float4* in4 = (const float4*)d_in[0];  // (64,1,224,224) float32
    const float*  wt  = (const float*)d_in[1];   // (1,4) float32
    float* out = (float*)d_out;                  // (64,4,223,223) float32

    dim3 grid((LY + TR - 1) / TR, 64);           // 14 x 64 = 896 blocks
    quanv_kernel<<<grid, 224>>>(in4, wt, out);
}

// round 14
// speedup vs baseline: 1.1382x; 1.0173x over previous
#include <cuda_runtime.h>

// Quanvolution (K=2, 4 qubits): analytic collapse to products of cos(pi*pix + w_q).
//   S_0={1,2,3}, S_1={0,1}, S_2={0,1,2}, S_3={0,1,2,3}
// R10 finding: TR=16 = 1.51 waves -> occ 48.6%, issue 21.8%: latency-bound from
// low residency, working set L2-resident (DRAM 11%). TR=8 restores 3.03 waves
// (1792 blocks, 87.5% theoretical occ). Register carry: rows r/r+1 share pixels,
// so each iteration loads only the 2 new-row pixels (2 LDS not 4).
// Output stores stay scalar (odd plane/row strides forbid wide STG).
// (R12/R13 were infra timeouts; identical resubmission.)

#define IN_W 224
#define IN_H 224
#define LY   223
#define TR   8          // output rows per block

__global__ __launch_bounds__(224) void quanv_kernel(
    const float4* __restrict__ in4,  // (B,1,224,224) viewed as float4
    const float* __restrict__ wt,    // (1,4)
    float* __restrict__ out)         // (B,4,223,223)
{
    const int t  = blockIdx.x;             // row tile [0,28)
    const int b  = blockIdx.y;             // batch
    const int y  = threadIdx.x;            // [0,224)
    const int x0 = min(t * TR, LY - TR);   // clamp: last tile overlaps by 1 row

    __shared__ float rows[TR + 1][IN_W];   // 9 x 224 floats = 8064 B

    // Stage TR+1 = 9 input rows (x0+8 <= 223 < IN_H, always in-bounds).
    const float4* base4 = in4 + ((size_t)b * IN_H + x0) * (IN_W / 4);
    float4* s4 = reinterpret_cast<float4*>(&rows[0][0]);
    #pragma unroll
    for (int f = 0; f < (TR + 1) * (IN_W / 4); f += 224) {
        int idx = f + y;
        if (idx < (TR + 1) * (IN_W / 4))
            s4[idx] = base4[idx];
    }

    const float w0 = wt[0];
    const float w1 = wt[1];
    const float w2 = wt[2];
    const float w3 = wt[3];

    __syncthreads();

    if (y < LY) {
        const float PI = 3.14159265358979323846f;
        const size_t plane = (size_t)LY * LY;
        float* o = out + (size_t)b * 4 * plane + (size_t)x0 * LY + y;

        // Prologue: top row of the tile through w0/w1.
        float p0 = rows[0][y];
        float p1 = rows[0][y + 1];
        float c0 = __cosf(fmaf(PI, p0, w0));
        float c1 = __cosf(fmaf(PI, p1, w1));

        #pragma unroll
        for (int r = 0; r < TR; r++) {
            // Load only the new (bottom) row's two pixels.
            float q0 = rows[r + 1][y];
            float q1 = rows[r + 1][y + 1];

            float g2 = __cosf(fmaf(PI, q0, w2));   // bottom row as w2
            float g3 = __cosf(fmaf(PI, q1, w3));   // bottom row as w3
            float n0 = __cosf(fmaf(PI, q0, w0));   // bottom row as next top (w0)
            float n1 = __cosf(fmaf(PI, q1, w1));   // bottom row as next top (w1)

            float g01  = c0 * c1;
            float g12  = c1 * g2;
            float g012 = g01 * g2;

            o[0]         = g12 * g3;   // q0: g1 g2 g3
            o[plane]     = g01;        // q1: g0 g1
            o[2 * plane] = g012;       // q2: g0 g1 g2
            o[3 * plane] = g012 * g3;  // q3: g0 g1 g2 g3

            c0 = n0;
            c1 = n1;
            o += LY;
        }
    }
}

extern "C" void kernel_launch(void* const* d_in, const int* in_sizes, int n_in,
                              void* d_out, int out_size)
{
    const float4* in4 = (const float4*)d_in[0];  // (64,1,224,224) float32
    const float*  wt  = (const float*)d_in[1];   // (1,4) float32
    float* out = (float*)d_out;                  // (64,4,223,223) float32

    dim3 grid((LY + TR - 1) / TR, 64);           // 28 x 64 = 1792 blocks
    quanv_kernel<<<grid, 224>>>(in4, wt, out);
}